// round 14
// baseline (speedup 1.0000x reference)
#include <cuda_runtime.h>
#include <cuda_fp16.h>
#include <cstdint>

#define BB 8
#define CI 128
#define MC 64
#define HH 64
#define WW 64
#define NH 128
#define NW 128
#define KTOT 576       // encoder GEMM K = 64c * 9taps
#define KC 48          // k per chunk (3 ksteps of 16)
#define NCH 12
#define A_CH16 6144    // u16 per A chunk: 8 mt * 3 ks * 32 lanes * 4 regs * 2
#define SMEM_ENC 51456 // kt alias (100*128 f32) dominates A+B images (24576 B)
#define CC3 32         // carafe channels per chunk
#define XP3 34         // carafe x_s c-minor padded stride

// Scratch (allocation-free per harness rules)
__device__ float g_m[BB * MC * HH * WW];                   // compressed features
__device__ float g_ker[BB * 25 * NH * NW];                 // softmax kernels
__device__ __align__(16) float g_cw2[CI * MC];             // compress weights [c][m]
__device__ __align__(16) uint16_t g_afrag[NCH * A_CH16];   // A fragment images (fp16)

typedef unsigned long long u64;

__device__ __forceinline__ u64 pk2(float lo, float hi) {
    u64 r; asm("mov.b64 %0, {%1,%2};" : "=l"(r) : "f"(lo), "f"(hi)); return r;
}
__device__ __forceinline__ float2 upk2(u64 v) {
    float2 f; asm("mov.b64 {%0,%1}, %2;" : "=f"(f.x), "=f"(f.y) : "l"(v)); return f;
}
__device__ __forceinline__ void fma2(u64 &acc, u64 a, u64 b) {
    asm("fma.rn.f32x2 %0, %1, %2, %0;" : "+l"(acc) : "l"(a), "l"(b));
}
__device__ __forceinline__ u64 ld2(const float* p) {
    return *reinterpret_cast<const u64*>(p);
}
__device__ __forceinline__ void mma16(float* d, const uint4 a, const uint2 b) {
    asm("mma.sync.aligned.m16n8k16.row.col.f32.f16.f16.f32 "
        "{%0,%1,%2,%3}, {%4,%5,%6,%7}, {%8,%9}, {%0,%1,%2,%3};"
        : "+f"(d[0]), "+f"(d[1]), "+f"(d[2]), "+f"(d[3])
        : "r"(a.x), "r"(a.y), "r"(a.z), "r"(a.w), "r"(b.x), "r"(b.y));
}

// ---------------------------------------------------------------------------
// Prep: encoder weights -> per-chunk fp16 fragment images; compress weights.
// ---------------------------------------------------------------------------
__global__ __launch_bounds__(256)
void k_prep(const float* __restrict__ ew, const float* __restrict__ cw) {
    int idx = blockIdx.x * 256 + threadIdx.x;
    if (idx < 128 * KTOT) {
        int o = idx / KTOT, k = idx - o * KTOT;
        float v = (o < 100) ? ew[o * KTOT + k] : 0.f;
        int ch = k / KC, kl = k - ch * KC;
        int ks = kl >> 4, kk = kl & 15;
        int mt = o >> 4, o16 = o & 15;
        int reg = ((kk >> 3) << 1) | (o16 >> 3);
        int lane = (o16 & 7) * 4 + ((kk >> 1) & 3);
        int half = kk & 1;
        int base = (((mt * 3 + ks) * 32 + lane) * 4 + reg) * 2 + half;
        g_afrag[ch * A_CH16 + base] = __half_as_ushort(__float2half_rn(v));
    } else if (idx < 128 * KTOT + CI * MC) {
        int j = idx - 128 * KTOT;
        g_cw2[j] = cw[(j & 63) * CI + (j >> 6)];
    }
}

// ---------------------------------------------------------------------------
// Kernel 1: 1x1 compress conv. block=(h-pair, b), 128 thr (R8 frozen).
// ---------------------------------------------------------------------------
extern __shared__ float sm1[];
__global__ __launch_bounds__(128)
void k_compress(const float* __restrict__ x, const float* __restrict__ cb) {
    float* xs = sm1;
    float* ws = sm1 + CI * 2 * 68;
    const int hb = blockIdx.x, b = blockIdx.y, tid = threadIdx.x;

    const float4* x4 = reinterpret_cast<const float4*>(x) + (size_t)b * (CI * HH * WW / 4);
    for (int idx = tid; idx < CI * 2 * 16; idx += 128) {
        int q = idx & 15, r = (idx >> 4) & 1, c = idx >> 5;
        float4 v = x4[(c * HH + 2 * hb + r) * 16 + q];
        *reinterpret_cast<float4*>(xs + (c * 2 + r) * 68 + q * 4) = v;
    }
    for (int idx = tid; idx < CI * MC / 4; idx += 128)
        reinterpret_cast<float4*>(ws)[idx] = reinterpret_cast<const float4*>(g_cw2)[idx];
    __syncthreads();

    const int mt = tid >> 4, wt = tid & 15;
    const int r = wt >> 3, w0 = (wt & 7) * 8, m0 = mt * 8;

    u64 acc[4][8];
    #pragma unroll
    for (int m = 0; m < 8; m++)
        #pragma unroll
        for (int wp = 0; wp < 4; wp++) acc[wp][m] = 0;

    #pragma unroll 2
    for (int c = 0; c < CI; c++) {
        const float* xr = xs + (c * 2 + r) * 68 + w0;
        u64 X0 = ld2(xr), X1 = ld2(xr + 2), X2 = ld2(xr + 4), X3 = ld2(xr + 6);
        const float* wr = ws + c * 64 + m0;
        #pragma unroll
        for (int m = 0; m < 8; m++) {
            float wv = wr[m];
            u64 W = pk2(wv, wv);
            fma2(acc[0][m], X0, W); fma2(acc[1][m], X1, W);
            fma2(acc[2][m], X2, W); fma2(acc[3][m], X3, W);
        }
    }
    #pragma unroll
    for (int m = 0; m < 8; m++) {
        float bv = cb[m0 + m];
        #pragma unroll
        for (int wp = 0; wp < 4; wp++) {
            float2 v = upk2(acc[wp][m]);
            *reinterpret_cast<float2*>(
                g_m + (((size_t)b * MC + m0 + m) * HH + 2 * hb + r) * WW + w0 + 2 * wp)
                = make_float2(v.x + bv, v.y + bv);
        }
    }
}

// ---------------------------------------------------------------------------
// Kernel 2: encoder conv as fp16 mma.sync GEMM + bias + softmax (R13 frozen).
// ---------------------------------------------------------------------------
__global__ __launch_bounds__(256, 2)
void k_encoder(const float* __restrict__ eb) {
    extern __shared__ __align__(16) uint32_t smE[];
    uint32_t* a_s = smE;
    uint32_t* b_s = smE + 3072;
    uint16_t* b_s16 = reinterpret_cast<uint16_t*>(b_s);
    float* kt = reinterpret_cast<float*>(smE);
    const int h2 = blockIdx.x, b = blockIdx.y, tid = threadIdx.x;
    const int wid = tid >> 5, lane = tid & 31;
    const int mg = wid >> 1, ngrp = wid & 1;
    const int gg = lane >> 2, tig = lane & 3;

    float acc[2][8][4];
    #pragma unroll
    for (int mt = 0; mt < 2; mt++)
        #pragma unroll
        for (int nt = 0; nt < 8; nt++)
            #pragma unroll
            for (int q = 0; q < 4; q++) acc[mt][nt][q] = 0.f;

    for (int ch = 0; ch < NCH; ch++) {
        __syncthreads();
        {
            const uint4* asrc = reinterpret_cast<const uint4*>(g_afrag + (size_t)ch * A_CH16);
            uint4* adst = reinterpret_cast<uint4*>(a_s);
            for (int idx = tid; idx < A_CH16 / 8; idx += 256) adst[idx] = asrc[idx];
        }
        for (int idx = tid; idx < KC * 128; idx += 256) {
            int n = idx & 127, kl = idx >> 7;
            int k = ch * KC + kl;
            int c = k / 9, rem = k - c * 9;
            int r = rem / 3, s = rem - r * 3;
            int p = n >> 6, w = n & 63;
            int hh = 2 * h2 + p + r - 1, col = w + s - 1;
            float v = 0.f;
            if ((unsigned)hh < HH && (unsigned)col < WW)
                v = g_m[(((size_t)b * MC + c) * HH + hh) * WW + col];
            int ks = kl >> 4, kk = kl & 15;
            int ntg = n >> 3, n8 = n & 7;
            int reg = kk >> 3;
            int lne = n8 * 4 + ((kk >> 1) & 3);
            b_s16[(((ks * 16 + ntg) * 32 + lne) * 2 + reg) * 2 + (kk & 1)] =
                __half_as_ushort(__float2half_rn(v));
        }
        __syncthreads();

        #pragma unroll
        for (int ks = 0; ks < 3; ks++) {
            uint4 A1[2];
            #pragma unroll
            for (int mt = 0; mt < 2; mt++) {
                int mtg = mg * 2 + mt;
                A1[mt] = *reinterpret_cast<const uint4*>(a_s + ((mtg * 3 + ks) * 32 + lane) * 4);
            }
            #pragma unroll
            for (int nt = 0; nt < 8; nt++) {
                int ntg = ngrp * 8 + nt;
                uint2 Bv = *reinterpret_cast<const uint2*>(b_s + ((ks * 16 + ntg) * 32 + lane) * 2);
                #pragma unroll
                for (int mt = 0; mt < 2; mt++)
                    mma16(acc[mt][nt], A1[mt], Bv);
            }
        }
    }
    __syncthreads();

    #pragma unroll
    for (int mt = 0; mt < 2; mt++) {
        #pragma unroll
        for (int nt = 0; nt < 8; nt++) {
            int o0 = (mg * 2 + mt) * 16 + gg;
            int n0 = (ngrp * 8 + nt) * 8 + 2 * tig;
            const float* c = acc[mt][nt];
            if (o0 < 100) {
                float bv = __ldg(eb + o0);
                kt[o0 * 128 + n0] = c[0] + bv;
                kt[o0 * 128 + n0 + 1] = c[1] + bv;
            }
            int o1 = o0 + 8;
            if (o1 < 100) {
                float bv = __ldg(eb + o1);
                kt[o1 * 128 + n0] = c[2] + bv;
                kt[o1 * 128 + n0 + 1] = c[3] + bv;
            }
        }
    }
    __syncthreads();

    for (int task = tid; task < 512; task += 256) {
        int w2 = task & 63, sub = (task >> 6) & 3, p = task >> 8;
        int colk = p * 64 + w2;
        int sh = sub >> 1, sw = sub & 1;
        float v[25]; float mx = -1e30f;
        #pragma unroll
        for (int t = 0; t < 25; t++) {
            v[t] = kt[(t * 4 + sub) * 128 + colk];
            mx = fmaxf(mx, v[t]);
        }
        float ssum = 0.f;
        #pragma unroll
        for (int t = 0; t < 25; t++) { v[t] = __expf(v[t] - mx); ssum += v[t]; }
        float inv = 1.f / ssum;
        int oh = 4 * h2 + 2 * p + sh, ow = 2 * w2 + sw;
        #pragma unroll
        for (int t = 0; t < 25; t++)
            g_ker[(((size_t)b * 25 + t) * NH + oh) * NW + ow] = v[t] * inv;
    }
}

// ---------------------------------------------------------------------------
// Kernel 3: content-aware reassembly v3. block=(h,b), 512 blocks, 256 thr.
// ker staged ONCE (25.6 KB); x in 4 chunks of 32 ch, c-minor stride-34
// (conflict-free ld2, ow-pair broadcast dedup). smem 71.8 KB -> 3 blocks/SM.
// Thread = (ow, cg): 16 ch per chunk as 8 c-pairs x 2 oh.
// ---------------------------------------------------------------------------
extern __shared__ float sm3[];
__global__ __launch_bounds__(256, 3)
void k_carafe(const float* __restrict__ x, float* __restrict__ out) {
    float* ker_s = sm3;              // 50*128 = 6400
    float* x_s   = sm3 + 6400;       // 5*68*XP3 = 11560
    const int h = blockIdx.x, b = blockIdx.y, tid = threadIdx.x;

    for (int idx = tid; idx < 50 * 32; idx += 256) {
        int q = idx & 31, tp = idx >> 5;
        *reinterpret_cast<float4*>(ker_s + tp * 128 + q * 4) =
            *reinterpret_cast<const float4*>(
                g_ker + (((size_t)b * 25 + (tp >> 1)) * NH + 2 * h + (tp & 1)) * NW + q * 4);
    }

    const int ow = tid & 127, cg = tid >> 7;   // cg 0..1 -> 16 ch per chunk
    const int w = ow >> 1;
    const float* kb = ker_s + ow;

    for (int c0 = 0; c0 < CI; c0 += CC3) {
        __syncthreads();
        // stage x chunk c-minor: [i][iw][c], stride XP3
        for (int idx = tid; idx < CC3 * 5 * 16; idx += 256) {
            int q = idx & 15, i = (idx >> 4) % 5, c = idx / 80;
            int hh = h + i - 2;
            float4 v = make_float4(0.f, 0.f, 0.f, 0.f);
            if ((unsigned)hh < HH)
                v = *reinterpret_cast<const float4*>(
                    x + (((size_t)b * CI + c0 + c) * HH + hh) * WW + q * 4);
            float* dst = x_s + (i * 68 + q * 4 + 2) * XP3 + c;
            dst[0] = v.x; dst[XP3] = v.y; dst[2 * XP3] = v.z; dst[3 * XP3] = v.w;
        }
        // zero halo iw in {0,1,66,67}
        for (int idx = tid; idx < 5 * 4 * CC3; idx += 256) {
            int c = idx % CC3, e = (idx / CC3) & 3, i = idx / (CC3 * 4);
            int iw = (e < 2) ? e : 64 + e;
            x_s[(i * 68 + iw) * XP3 + c] = 0.f;
        }
        __syncthreads();

        const float* xb = x_s + w * XP3 + cg * 16;
        u64 acc[2][8];
        #pragma unroll
        for (int p = 0; p < 2; p++)
            #pragma unroll
            for (int cp = 0; cp < 8; cp++) acc[p][cp] = 0;

        #pragma unroll
        for (int i = 0; i < 5; i++) {
            #pragma unroll
            for (int j = 0; j < 5; j++) {
                const int t = i * 5 + j;
                float k0 = kb[(2 * t) * 128];
                float k1 = kb[(2 * t + 1) * 128];
                u64 K0 = pk2(k0, k0), K1 = pk2(k1, k1);
                const float* xp = xb + (i * 68 + j) * XP3;
                #pragma unroll
                for (int cp = 0; cp < 8; cp++) {
                    u64 X = ld2(xp + 2 * cp);
                    fma2(acc[0][cp], X, K0);
                    fma2(acc[1][cp], X, K1);
                }
            }
        }
        #pragma unroll
        for (int p = 0; p < 2; p++)
            #pragma unroll
            for (int cp = 0; cp < 8; cp++) {
                float2 v = upk2(acc[p][cp]);
                int ch = c0 + cg * 16 + 2 * cp;
                size_t base = (((size_t)b * CI + ch) * NH + 2 * h + p) * NW + ow;
                out[base] = v.x;
                out[base + (size_t)NH * NW] = v.y;
            }
    }
}

// ---------------------------------------------------------------------------
extern "C" void kernel_launch(void* const* d_in, const int* in_sizes, int n_in,
                              void* d_out, int out_size) {
    const float* x  = (const float*)d_in[0];
    const float* cw = (const float*)d_in[1];
    const float* cb = (const float*)d_in[2];
    const float* ew = (const float*)d_in[3];
    const float* eb = (const float*)d_in[4];
    float* out = (float*)d_out;

    const int smem1 = (CI * 2 * 68 + CI * MC) * 4;     // 102400
    const int smem3 = (6400 + 5 * 68 * XP3) * 4;       // 71840
    cudaFuncSetAttribute(k_compress, cudaFuncAttributeMaxDynamicSharedMemorySize, smem1);
    cudaFuncSetAttribute(k_encoder,  cudaFuncAttributeMaxDynamicSharedMemorySize, SMEM_ENC);
    cudaFuncSetAttribute(k_carafe,   cudaFuncAttributeMaxDynamicSharedMemorySize, smem3);

    k_prep<<<(128 * KTOT + CI * MC + 255) / 256, 256>>>(ew, cw);
    k_compress<<<dim3(HH / 2, BB), 128, smem1>>>(x, cb);
    k_encoder<<<dim3(HH / 2, BB), 256, SMEM_ENC>>>(eb);
    k_carafe<<<dim3(HH, BB), 256, smem3>>>(x, out);
}

// round 16
// speedup vs baseline: 1.1358x; 1.1358x over previous
#include <cuda_runtime.h>
#include <cuda_fp16.h>
#include <cstdint>

#define BB 8
#define CI 128
#define MC 64
#define HH 64
#define WW 64
#define NH 128
#define NW 128
#define A_CH16 8192    // fp16 per encoder A chunk: 8 mt * 4 ks * 32 lanes * 8
#define SMEM_ENC 51456 // kt alias (100*128 f32) covers A+B images (32 KB)
#define SMEM_CMP 49152 // compress: A 16 KB + B 32 KB
#define CC3 32         // carafe channels per chunk
#define XP3 34         // carafe x_s c-minor padded stride

// Scratch (allocation-free per harness rules)
__device__ __half g_mh[BB * MC * HH * WW];                 // compressed features (fp16)
__device__ float g_ker[BB * 25 * NH * NW];                 // softmax kernels
__device__ __align__(16) uint16_t g_afrag[9 * A_CH16];     // encoder A frags (per-tap chunks)
__device__ __align__(16) uint16_t g_cwfrag[8192];          // compress A frags

typedef unsigned long long u64;

__device__ __forceinline__ u64 pk2(float lo, float hi) {
    u64 r; asm("mov.b64 %0, {%1,%2};" : "=l"(r) : "f"(lo), "f"(hi)); return r;
}
__device__ __forceinline__ float2 upk2(u64 v) {
    float2 f; asm("mov.b64 {%0,%1}, %2;" : "=f"(f.x), "=f"(f.y) : "l"(v)); return f;
}
__device__ __forceinline__ void fma2(u64 &acc, u64 a, u64 b) {
    asm("fma.rn.f32x2 %0, %1, %2, %0;" : "+l"(acc) : "l"(a), "l"(b));
}
__device__ __forceinline__ u64 ld2(const float* p) {
    return *reinterpret_cast<const u64*>(p);
}
__device__ __forceinline__ void mma16(float* d, const uint4 a, const uint2 b) {
    asm("mma.sync.aligned.m16n8k16.row.col.f32.f16.f16.f32 "
        "{%0,%1,%2,%3}, {%4,%5,%6,%7}, {%8,%9}, {%0,%1,%2,%3};"
        : "+f"(d[0]), "+f"(d[1]), "+f"(d[2]), "+f"(d[3])
        : "r"(a.x), "r"(a.y), "r"(a.z), "r"(a.w), "r"(b.x), "r"(b.y));
}

// ---------------------------------------------------------------------------
// Prep: encoder weights -> per-tap fp16 fragment chunks (k = tap*64 + c);
// compress weights -> fp16 fragment image.
// ---------------------------------------------------------------------------
__global__ __launch_bounds__(256)
void k_prep(const float* __restrict__ ew, const float* __restrict__ cw) {
    int idx = blockIdx.x * 256 + threadIdx.x;
    if (idx < 128 * 576) {
        int o = idx / 576, rem = idx - o * 576;
        int c = rem / 9, tap = rem - c * 9;
        float v = (o < 100) ? ew[idx] : 0.f;
        int mt = o >> 4, o16 = o & 15;
        int ks = c >> 4, kk = c & 15;
        int reg = ((kk >> 3) << 1) | (o16 >> 3);
        int lane = (o16 & 7) * 4 + ((kk >> 1) & 3);
        int base = (((mt * 4 + ks) * 32 + lane) * 4 + reg) * 2 + (kk & 1);
        g_afrag[tap * A_CH16 + base] = __half_as_ushort(__float2half_rn(v));
    } else if (idx < 128 * 576 + 64 * 128) {
        int j = idx - 128 * 576;
        int m = j >> 7, c = j & 127;
        int mt = m >> 4, o16 = m & 15;
        int ks = c >> 4, kk = c & 15;
        int reg = ((kk >> 3) << 1) | (o16 >> 3);
        int lane = (o16 & 7) * 4 + ((kk >> 1) & 3);
        int base = (((mt * 8 + ks) * 32 + lane) * 4 + reg) * 2 + (kk & 1);
        g_cwfrag[base] = __half_as_ushort(__float2half_rn(cw[j]));
    }
}

// ---------------------------------------------------------------------------
// Kernel 1: 1x1 compress conv as fp16 mma GEMM. block=(hb,b), 256 thr.
// D[64m, 128n] = W[64,128] * X[128, n], n = r*64 + w over the h-pair.
// smem: A 16 KB + B 32 KB = 48 KB. Warps = 2 m-groups x 4 n-groups.
// ---------------------------------------------------------------------------
__global__ __launch_bounds__(256)
void k_compress(const float* __restrict__ x, const float* __restrict__ cb) {
    extern __shared__ __align__(16) uint32_t smC[];
    uint32_t* a_s = smC;             // 4096 u32 (16 KB)
    uint32_t* b_s = smC + 4096;      // 8192 u32 (32 KB)
    uint16_t* b_s16 = reinterpret_cast<uint16_t*>(b_s);
    const int hb = blockIdx.x, b = blockIdx.y, tid = threadIdx.x;
    const int wid = tid >> 5, lane = tid & 31;
    const int mg = wid >> 2, ngrp = wid & 3;
    const int gg = lane >> 2, tig = lane & 3;

    // stage compress A frags (16 KB)
    {
        const uint4* src = reinterpret_cast<const uint4*>(g_cwfrag);
        uint4* dst = reinterpret_cast<uint4*>(a_s);
        for (int i = tid; i < 1024; i += 256) dst[i] = src[i];
    }
    // build B frags from x (fp32 -> fp16)
    const float4* x4 = reinterpret_cast<const float4*>(x) + (size_t)b * (CI * HH * WW / 4);
    for (int it = 0; it < 16; it++) {
        int idx = tid + it * 256;
        int q = idx & 15, r = (idx >> 4) & 1, c = idx >> 5;
        float4 v = x4[(c * HH + 2 * hb + r) * 16 + q];
        int kk = c & 15, ks = c >> 4;
        int reg = kk >> 3, half = kk & 1;
        int lsel = (kk >> 1) & 3;
        float vv[4] = {v.x, v.y, v.z, v.w};
        #pragma unroll
        for (int j = 0; j < 4; j++) {
            int n = r * 64 + q * 4 + j;
            int lne = (n & 7) * 4 + lsel;
            b_s16[(((ks * 16 + (n >> 3)) * 32 + lne) * 2 + reg) * 2 + half] =
                __half_as_ushort(__float2half_rn(vv[j]));
        }
    }
    __syncthreads();

    float acc[2][4][4];
    #pragma unroll
    for (int mt = 0; mt < 2; mt++)
        #pragma unroll
        for (int nt = 0; nt < 4; nt++)
            #pragma unroll
            for (int q = 0; q < 4; q++) acc[mt][nt][q] = 0.f;

    #pragma unroll
    for (int ks = 0; ks < 8; ks++) {
        uint4 A1[2];
        #pragma unroll
        for (int mt = 0; mt < 2; mt++) {
            int mtg = mg * 2 + mt;
            A1[mt] = *reinterpret_cast<const uint4*>(a_s + ((mtg * 8 + ks) * 32 + lane) * 4);
        }
        #pragma unroll
        for (int nt = 0; nt < 4; nt++) {
            int ntg = ngrp * 4 + nt;
            uint2 Bv = *reinterpret_cast<const uint2*>(b_s + ((ks * 16 + ntg) * 32 + lane) * 2);
            #pragma unroll
            for (int mt = 0; mt < 2; mt++)
                mma16(acc[mt][nt], A1[mt], Bv);
        }
    }

    // writeout to g_mh (fp16) with bias
    #pragma unroll
    for (int mt = 0; mt < 2; mt++) {
        #pragma unroll
        for (int nt = 0; nt < 4; nt++) {
            int o0 = (mg * 2 + mt) * 16 + gg;
            int n0 = (ngrp * 4 + nt) * 8 + 2 * tig;
            int r = n0 >> 6, w = n0 & 63;
            const float* c = acc[mt][nt];
            float b0 = cb[o0], b1 = cb[o0 + 8];
            __half2* dst0 = reinterpret_cast<__half2*>(
                g_mh + (((size_t)b * MC + o0) * HH + 2 * hb + r) * WW + w);
            *dst0 = __floats2half2_rn(c[0] + b0, c[1] + b0);
            __half2* dst1 = reinterpret_cast<__half2*>(
                g_mh + (((size_t)b * MC + o0 + 8) * HH + 2 * hb + r) * WW + w);
            *dst1 = __floats2half2_rn(c[2] + b1, c[3] + b1);
        }
    }
}

// ---------------------------------------------------------------------------
// Kernel 2: encoder conv as fp16 mma GEMM + bias + softmax. k = tap*64 + c,
// 9 chunks (one tap each, 4 k16-steps). B-build: predicated ushort copies
// from g_mh, no cvt, no div. Warps = 4 m-groups x 2 n-groups.
// ---------------------------------------------------------------------------
__global__ __launch_bounds__(256, 2)
void k_encoder(const float* __restrict__ eb) {
    extern __shared__ __align__(16) uint32_t smE[];
    uint32_t* a_s = smE;             // 4096 u32
    uint32_t* b_s = smE + 4096;      // 4096 u32
    uint16_t* b_s16 = reinterpret_cast<uint16_t*>(b_s);
    float* kt = reinterpret_cast<float*>(smE);
    const int h2 = blockIdx.x, b = blockIdx.y, tid = threadIdx.x;
    const int wid = tid >> 5, lane = tid & 31;
    const int mg = wid >> 1, ngrp = wid & 1;
    const int gg = lane >> 2, tig = lane & 3;

    float acc[2][8][4];
    #pragma unroll
    for (int mt = 0; mt < 2; mt++)
        #pragma unroll
        for (int nt = 0; nt < 8; nt++)
            #pragma unroll
            for (int q = 0; q < 4; q++) acc[mt][nt][q] = 0.f;

    #pragma unroll 1
    for (int tap = 0; tap < 9; tap++) {
        const int r = tap / 3, s = tap - r * 3;
        __syncthreads();
        // stage A chunk (16 KB)
        {
            const uint4* src = reinterpret_cast<const uint4*>(g_afrag + (size_t)tap * A_CH16);
            uint4* dst = reinterpret_cast<uint4*>(a_s);
            for (int i = tid; i < 1024; i += 256) dst[i] = src[i];
        }
        // build B frags: B[n][c] = m[c][2h2+p+r-1][w+s-1] (fp16 passthrough)
        #pragma unroll 4
        for (int it = 0; it < 32; it++) {
            int idx = tid + it * 256;
            int n = idx & 127, c = idx >> 7;
            int p = n >> 6, w = n & 63;
            int hh = 2 * h2 + p + r - 1, col = w + s - 1;
            uint16_t v = 0;
            if ((unsigned)hh < HH && (unsigned)col < WW)
                v = reinterpret_cast<const uint16_t*>(g_mh)
                        [(((size_t)b * MC + c) * HH + hh) * WW + col];
            int kk = c & 15, ks = c >> 4;
            int lne = (n & 7) * 4 + ((kk >> 1) & 3);
            b_s16[(((ks * 16 + (n >> 3)) * 32 + lne) * 2 + (kk >> 3)) * 2 + (kk & 1)] = v;
        }
        __syncthreads();

        #pragma unroll
        for (int ks = 0; ks < 4; ks++) {
            uint4 A1[2];
            #pragma unroll
            for (int mt = 0; mt < 2; mt++) {
                int mtg = mg * 2 + mt;
                A1[mt] = *reinterpret_cast<const uint4*>(a_s + ((mtg * 4 + ks) * 32 + lane) * 4);
            }
            #pragma unroll
            for (int nt = 0; nt < 8; nt++) {
                int ntg = ngrp * 8 + nt;
                uint2 Bv = *reinterpret_cast<const uint2*>(b_s + ((ks * 16 + ntg) * 32 + lane) * 2);
                #pragma unroll
                for (int mt = 0; mt < 2; mt++)
                    mma16(acc[mt][nt], A1[mt], Bv);
            }
        }
    }
    __syncthreads();

    #pragma unroll
    for (int mt = 0; mt < 2; mt++) {
        #pragma unroll
        for (int nt = 0; nt < 8; nt++) {
            int o0 = (mg * 2 + mt) * 16 + gg;
            int n0 = (ngrp * 8 + nt) * 8 + 2 * tig;
            const float* c = acc[mt][nt];
            if (o0 < 100) {
                float bv = __ldg(eb + o0);
                kt[o0 * 128 + n0] = c[0] + bv;
                kt[o0 * 128 + n0 + 1] = c[1] + bv;
            }
            int o1 = o0 + 8;
            if (o1 < 100) {
                float bv = __ldg(eb + o1);
                kt[o1 * 128 + n0] = c[2] + bv;
                kt[o1 * 128 + n0 + 1] = c[3] + bv;
            }
        }
    }
    __syncthreads();

    for (int task = tid; task < 512; task += 256) {
        int w2 = task & 63, sub = (task >> 6) & 3, p = task >> 8;
        int colk = p * 64 + w2;
        int sh = sub >> 1, sw = sub & 1;
        float v[25]; float mx = -1e30f;
        #pragma unroll
        for (int t = 0; t < 25; t++) {
            v[t] = kt[(t * 4 + sub) * 128 + colk];
            mx = fmaxf(mx, v[t]);
        }
        float ssum = 0.f;
        #pragma unroll
        for (int t = 0; t < 25; t++) { v[t] = __expf(v[t] - mx); ssum += v[t]; }
        float inv = 1.f / ssum;
        int oh = 4 * h2 + 2 * p + sh, ow = 2 * w2 + sw;
        #pragma unroll
        for (int t = 0; t < 25; t++)
            g_ker[(((size_t)b * 25 + t) * NH + oh) * NW + ow] = v[t] * inv;
    }
}

// ---------------------------------------------------------------------------
// Kernel 3: content-aware reassembly (R13 v3, frozen). block=(h,b), 256 thr.
// ---------------------------------------------------------------------------
extern __shared__ float sm3[];
__global__ __launch_bounds__(256, 3)
void k_carafe(const float* __restrict__ x, float* __restrict__ out) {
    float* ker_s = sm3;              // 50*128 = 6400
    float* x_s   = sm3 + 6400;       // 5*68*XP3 = 11560
    const int h = blockIdx.x, b = blockIdx.y, tid = threadIdx.x;

    for (int idx = tid; idx < 50 * 32; idx += 256) {
        int q = idx & 31, tp = idx >> 5;
        *reinterpret_cast<float4*>(ker_s + tp * 128 + q * 4) =
            *reinterpret_cast<const float4*>(
                g_ker + (((size_t)b * 25 + (tp >> 1)) * NH + 2 * h + (tp & 1)) * NW + q * 4);
    }

    const int ow = tid & 127, cg = tid >> 7;
    const int w = ow >> 1;
    const float* kb = ker_s + ow;

    for (int c0 = 0; c0 < CI; c0 += CC3) {
        __syncthreads();
        for (int idx = tid; idx < CC3 * 5 * 16; idx += 256) {
            int q = idx & 15, i = (idx >> 4) % 5, c = idx / 80;
            int hh = h + i - 2;
            float4 v = make_float4(0.f, 0.f, 0.f, 0.f);
            if ((unsigned)hh < HH)
                v = *reinterpret_cast<const float4*>(
                    x + (((size_t)b * CI + c0 + c) * HH + hh) * WW + q * 4);
            float* dst = x_s + (i * 68 + q * 4 + 2) * XP3 + c;
            dst[0] = v.x; dst[XP3] = v.y; dst[2 * XP3] = v.z; dst[3 * XP3] = v.w;
        }
        for (int idx = tid; idx < 5 * 4 * CC3; idx += 256) {
            int c = idx % CC3, e = (idx / CC3) & 3, i = idx / (CC3 * 4);
            int iw = (e < 2) ? e : 64 + e;
            x_s[(i * 68 + iw) * XP3 + c] = 0.f;
        }
        __syncthreads();

        const float* xb = x_s + w * XP3 + cg * 16;
        u64 acc[2][8];
        #pragma unroll
        for (int p = 0; p < 2; p++)
            #pragma unroll
            for (int cp = 0; cp < 8; cp++) acc[p][cp] = 0;

        #pragma unroll
        for (int i = 0; i < 5; i++) {
            #pragma unroll
            for (int j = 0; j < 5; j++) {
                const int t = i * 5 + j;
                float k0 = kb[(2 * t) * 128];
                float k1 = kb[(2 * t + 1) * 128];
                u64 K0 = pk2(k0, k0), K1 = pk2(k1, k1);
                const float* xp = xb + (i * 68 + j) * XP3;
                #pragma unroll
                for (int cp = 0; cp < 8; cp++) {
                    u64 X = ld2(xp + 2 * cp);
                    fma2(acc[0][cp], X, K0);
                    fma2(acc[1][cp], X, K1);
                }
            }
        }
        #pragma unroll
        for (int p = 0; p < 2; p++)
            #pragma unroll
            for (int cp = 0; cp < 8; cp++) {
                float2 v = upk2(acc[p][cp]);
                int ch = c0 + cg * 16 + 2 * cp;
                size_t base = (((size_t)b * CI + ch) * NH + 2 * h + p) * NW + ow;
                out[base] = v.x;
                out[base + (size_t)NH * NW] = v.y;
            }
    }
}

// ---------------------------------------------------------------------------
extern "C" void kernel_launch(void* const* d_in, const int* in_sizes, int n_in,
                              void* d_out, int out_size) {
    const float* x  = (const float*)d_in[0];
    const float* cw = (const float*)d_in[1];
    const float* cb = (const float*)d_in[2];
    const float* ew = (const float*)d_in[3];
    const float* eb = (const float*)d_in[4];
    float* out = (float*)d_out;

    const int smem3 = (6400 + 5 * 68 * XP3) * 4;       // 71840
    cudaFuncSetAttribute(k_compress, cudaFuncAttributeMaxDynamicSharedMemorySize, SMEM_CMP);
    cudaFuncSetAttribute(k_encoder,  cudaFuncAttributeMaxDynamicSharedMemorySize, SMEM_ENC);
    cudaFuncSetAttribute(k_carafe,   cudaFuncAttributeMaxDynamicSharedMemorySize, smem3);

    k_prep<<<(128 * 576 + 64 * 128 + 255) / 256, 256>>>(ew, cw);
    k_compress<<<dim3(HH / 2, BB), 256, SMEM_CMP>>>(x, cb);
    k_encoder<<<dim3(HH / 2, BB), 256, SMEM_ENC>>>(eb);
    k_carafe<<<dim3(HH, BB), 256, smem3>>>(x, out);
}